// round 7
// baseline (speedup 1.0000x reference)
#include <cuda_runtime.h>

// XAJ hydrological scan: T=730, B=16384, evap MLP 8->16->8->1.
// Round 7: R1 structure (1 basin/thread, 512 warps, scalar everywhere) with
// exactly ONE change class: layer 2 uses packed fma.rn.f32x2 sourced directly
// from LDS.128 float4 pairs (zero extra persistent registers), because the
// FMA pipe (rt2/SMSP) is the measured floor and FFMA2 has rt=1. Tail uses
// fdividef + explicit ex2/lg2 (drops the IEEE-div sequence R1 paid for).
#define T_STEPS 730
#define NBASIN  16384
#define NH1     16
#define NH2     8
#define EPSV    1e-5f

// Packed 2xFP32 FMA (sm_100+; PTX-only). Bit-identical to two fmaf's.
__device__ __forceinline__ float2 ffma2(float2 a, float2 b, float2 c) {
    float2 d;
    asm("fma.rn.f32x2 %0, %1, %2, %3;"
        : "=l"(reinterpret_cast<unsigned long long&>(d))
        : "l"(reinterpret_cast<unsigned long long&>(a)),
          "l"(reinterpret_cast<unsigned long long&>(b)),
          "l"(reinterpret_cast<unsigned long long&>(c)));
    return d;
}
// Duplicate a scalar into both lanes of an aligned pair (1 MOV, ALU pipe).
__device__ __forceinline__ float2 dup2(float s) {
    float2 d;
    asm("mov.b64 %0, {%1, %1};"
        : "=l"(reinterpret_cast<unsigned long long&>(d)) : "f"(s));
    return d;
}
// MUFU.EX2 / MUFU.LG2 — the ops __expf/__powf decompose into.
__device__ __forceinline__ float ex2f(float x) {
    float r; asm("ex2.approx.f32 %0, %1;" : "=f"(r) : "f"(x)); return r;
}
__device__ __forceinline__ float lg2f(float x) {
    float r; asm("lg2.approx.f32 %0, %1;" : "=f"(r) : "f"(x)); return r;
}

__global__ __launch_bounds__(128, 1)
void xaj_dpl7_kernel(const float2* __restrict__ p_and_e,
                     const float*  __restrict__ kc_,
                     const float*  __restrict__ um_,
                     const float*  __restrict__ lm_,
                     const float*  __restrict__ dm_,
                     const float*  __restrict__ b_,
                     const float*  __restrict__ im_,
                     const float*  __restrict__ c_,
                     const float*  __restrict__ w0_,
                     const float*  __restrict__ W1,
                     const float*  __restrict__ b1,
                     const float*  __restrict__ W2,
                     const float*  __restrict__ b2,
                     const float*  __restrict__ W3,
                     const float*  __restrict__ b3,
                     float4*       __restrict__ out)
{
    // W2 [16,8] broadcast from shared via LDS.128.
    __shared__ float sW2[NH1 * NH2];
    if (threadIdx.x < NH1 * NH2) sW2[threadIdx.x] = W2[threadIdx.x];
    __syncthreads();

    const int bas = blockIdx.x * blockDim.x + threadIdx.x;

    // Per-basin constants (all scalar — R1-proven register layout)
    const float kc = kc_[bas];
    const float um = um_[bas];
    const float lm = lm_[bas];
    const float dm = dm_[bas];
    const float bb = b_[bas];
    const float im = im_[bas];
    const float cc = c_[bas];
    float w = w0_[bas];

    const float wm      = um + lm + dm;
    const float one_b   = 1.0f + bb;
    const float wmm     = wm * one_b;
    const float inv_b1  = 1.0f / one_b;
    const float inv_wm  = 1.0f / wm;
    const float inv_wmm = 1.0f / wmm;
    const float wm_eps  = wm - EPSV;

    // Layer-1: constant features folded into h1b; live rows scalar (R1 layout).
    float h1b[NH1], w5[NH1], w6[NH1], w7[NH1];
#pragma unroll
    for (int i = 0; i < NH1; i++) {
        h1b[i] = b1[i] + kc * W1[i] + um * W1[NH1 + i] + lm * W1[2 * NH1 + i]
               + dm * W1[3 * NH1 + i] + cc * W1[4 * NH1 + i];
        w5[i] = W1[5 * NH1 + i];
        w6[i] = W1[6 * NH1 + i];
        w7[i] = W1[7 * NH1 + i];
    }
    // Layer-2 bias as pair-aligned float2 (seeds the packed accumulators).
    float2 rb2p[4];
#pragma unroll
    for (int k = 0; k < 4; k++) rb2p[k] = make_float2(b2[2 * k], b2[2 * k + 1]);
    float rw3[NH2];
#pragma unroll
    for (int k = 0; k < NH2; k++) rw3[k] = W3[k];
    const float rb3 = b3[0];

    // Forcing: distance-2 prefetch (hides ~577-cyc DRAM latency).
    const float2* pe_ptr = p_and_e + bas;
    float2 pe_a = pe_ptr[0];
    float2 pe_b = pe_ptr[NBASIN];

    float4* out_ptr = out + bas;

#pragma unroll 2
    for (int t = 0; t < T_STEPS; t++) {
        const float2 pe = pe_a;
        pe_a = pe_b;
        if (t + 2 < T_STEPS) pe_b = pe_ptr[(size_t)(t + 2) * NBASIN];

        const float prcp = fmaxf(pe.x, 0.0f);
        const float pet  = fmaxf(pe.y, 0.0f);
        const float kpet = kc * pet;
        const float w0c  = fminf(fmaxf(w, 0.0f), wm_eps);

        // Off-chain early: lg2 half of powf(frac, inv_b1) right after w0c.
        const float frac   = fminf(fmaxf(fmaf(-w0c, inv_wm, 1.0f), EPSV), 1.0f);
        const float a_xaj  = wmm * (1.0f - ex2f(inv_b1 * lg2f(frac)));
        const float r_base = w0c - wm;               // r_full = pe_net + r_base

        // ---- layer 1: scalar (R1-proven) ----
        float h[NH1];
#pragma unroll
        for (int i = 0; i < NH1; i++) {
            float hh = h1b[i] + w0c * w5[i] + prcp * w6[i] + pet * w7[i];
            h[i] = fmaxf(hh, 0.0f);
        }

        // ---- layer 2: 16x8 matvec as FFMA2 (rt=1), weights straight from LDS.128 ----
        float2 a01 = rb2p[0], a23 = rb2p[1], a45 = rb2p[2], a67 = rb2p[3];
#pragma unroll
        for (int j = 0; j < NH1; j++) {
            const float4 wA = *reinterpret_cast<const float4*>(&sW2[j * NH2]);
            const float4 wB = *reinterpret_cast<const float4*>(&sW2[j * NH2 + 4]);
            const float2 hd = dup2(h[j]);
            a01 = ffma2(hd, *reinterpret_cast<const float2*>(&wA.x), a01);
            a23 = ffma2(hd, *reinterpret_cast<const float2*>(&wA.z), a23);
            a45 = ffma2(hd, *reinterpret_cast<const float2*>(&wB.x), a45);
            a67 = ffma2(hd, *reinterpret_cast<const float2*>(&wB.z), a67);
        }

        // ---- layer 3 (scalar tree) ----
        float y0 = rb3 + fmaxf(a01.x, 0.0f) * rw3[0];
        float y1 = fmaxf(a01.y, 0.0f) * rw3[1];
        float y2 = fmaxf(a23.x, 0.0f) * rw3[2];
        float y3 = fmaxf(a23.y, 0.0f) * rw3[3];
        y0 += fmaxf(a45.x, 0.0f) * rw3[4];
        y1 += fmaxf(a45.y, 0.0f) * rw3[5];
        y2 += fmaxf(a67.x, 0.0f) * rw3[6];
        y3 += fmaxf(a67.y, 0.0f) * rw3[7];
        const float y = (y0 + y1) + (y2 + y3);

        // sigmoid * kc * pet:  e = kpet / (1 + exp(-y))  (MUFU EX2 + MUFU RCP)
        const float ex = ex2f(-1.442695040888963f * y);
        const float e  = __fdividef(kpet, 1.0f + ex);

        // ---- XAJ water balance ----
        const float pd     = prcp - e;
        const float pe_net = fmaxf(pd, 0.0f);
        const float resid  = fminf(fmaxf(fmaf(-(pe_net + a_xaj), inv_wmm, 1.0f), 0.0f), 1.0f);
        // resid==0 exactly when pe_net + a >= wmm; ex2(one_b*lg2(0)) = 0,
        // so this is branchlessly identical to the reference's where().
        const float rp  = ex2f(one_b * lg2f(resid));
        const float r   = fmaxf(pe_net + r_base + wm * rp, 0.0f);
        const float rim = pe_net * im;

        w = fminf(fmaxf(w0c + pd - r, 0.0f), wm_eps);

        out_ptr[0] = make_float4(r, rim, e, pe_net);
        out_ptr += NBASIN;
    }
}

extern "C" void kernel_launch(void* const* d_in, const int* in_sizes, int n_in,
                              void* d_out, int out_size)
{
    (void)in_sizes; (void)n_in; (void)out_size;
    const float2* p_and_e = (const float2*)d_in[0];
    const float*  kc = (const float*)d_in[1];
    const float*  um = (const float*)d_in[2];
    const float*  lm = (const float*)d_in[3];
    const float*  dm = (const float*)d_in[4];
    const float*  b  = (const float*)d_in[5];
    const float*  im = (const float*)d_in[6];
    const float*  c  = (const float*)d_in[7];
    const float*  w0 = (const float*)d_in[8];
    const float*  W1 = (const float*)d_in[9];
    const float*  b1 = (const float*)d_in[10];
    const float*  W2 = (const float*)d_in[11];
    const float*  b2 = (const float*)d_in[12];
    const float*  W3 = (const float*)d_in[13];
    const float*  b3 = (const float*)d_in[14];
    float4* out = (float4*)d_out;

    // 16384 threads = 512 warps, 1 basin/thread (lowest FMA-work per basin),
    // 128 blocks x 128 threads = 4 warps/SM on 128 SMs (R1-proven shape).
    xaj_dpl7_kernel<<<128, 128>>>(p_and_e, kc, um, lm, dm, b, im, c, w0,
                                  W1, b1, W2, b2, W3, b3, out);
}

// round 8
// speedup vs baseline: 1.2069x; 1.2069x over previous
#include <cuda_runtime.h>

// XAJ hydrological scan: T=730, B=16384, evap MLP 8->16->8->1.
// Round 8: R1's proven scalar structure + cross-step software pipelining.
// The forcing-only layer-1 partial pre[i] = h1b[i] + prcp*w6[i] + pet*w7[i]
// for step t+1 is computed inside step t's serial MUFU tail (sigmoid + two
// pow chains), so layer 1 on the critical path is just 16 FFMAs. w6/w7 move
// to shared (basin-uniform) to pay for pre[16] in registers. All scalar —
// fma.rn.f32x2 is abandoned (3 rounds: reg-allocator blowup to 254, no win).
#define T_STEPS 730
#define NBASIN  16384
#define NH1     16
#define NH2     8
#define EPSV    1e-5f

// MUFU.EX2 / MUFU.LG2 — the ops __expf/__powf decompose into.
__device__ __forceinline__ float ex2f(float x) {
    float r; asm("ex2.approx.f32 %0, %1;" : "=f"(r) : "f"(x)); return r;
}
__device__ __forceinline__ float lg2f(float x) {
    float r; asm("lg2.approx.f32 %0, %1;" : "=f"(r) : "f"(x)); return r;
}

__global__ __launch_bounds__(128, 1)
void xaj_dpl8_kernel(const float2* __restrict__ p_and_e,
                     const float*  __restrict__ kc_,
                     const float*  __restrict__ um_,
                     const float*  __restrict__ lm_,
                     const float*  __restrict__ dm_,
                     const float*  __restrict__ b_,
                     const float*  __restrict__ im_,
                     const float*  __restrict__ c_,
                     const float*  __restrict__ w0_,
                     const float*  __restrict__ W1,
                     const float*  __restrict__ b1,
                     const float*  __restrict__ W2,
                     const float*  __restrict__ b2,
                     const float*  __restrict__ W3,
                     const float*  __restrict__ b3,
                     float4*       __restrict__ out)
{
    // Shared: W2 [16,8] (LDS.128 broadcast rows) + W1 rows 6,7 (prcp/pet rows,
    // basin-uniform, read only in the tail shadow).
    __shared__ float sW2[NH1 * NH2];
    __shared__ float sW6[NH1];
    __shared__ float sW7[NH1];
    if (threadIdx.x < NH1 * NH2) sW2[threadIdx.x] = W2[threadIdx.x];
    if (threadIdx.x < NH1) {
        sW6[threadIdx.x] = W1[6 * NH1 + threadIdx.x];
        sW7[threadIdx.x] = W1[7 * NH1 + threadIdx.x];
    }
    __syncthreads();

    const int bas = blockIdx.x * blockDim.x + threadIdx.x;

    // Per-basin constants (scalar, R1-proven layout)
    const float kc = kc_[bas];
    const float um = um_[bas];
    const float lm = lm_[bas];
    const float dm = dm_[bas];
    const float bb = b_[bas];
    const float im = im_[bas];
    const float cc = c_[bas];
    float w = w0_[bas];

    const float wm      = um + lm + dm;
    const float one_b   = 1.0f + bb;
    const float wmm     = wm * one_b;
    const float inv_b1  = 1.0f / one_b;
    const float inv_wm  = 1.0f / wm;
    const float inv_wmm = 1.0f / wmm;
    const float wm_eps  = wm - EPSV;

    // w5 (w0c row) stays in registers: it's on the critical path.
    // h1b folds the 5 constant features. pre[] is the pipelined partial.
    float w5[NH1], h1b[NH1], pre[NH1];
#pragma unroll
    for (int i = 0; i < NH1; i++) {
        w5[i] = W1[5 * NH1 + i];
        h1b[i] = b1[i] + kc * W1[i] + um * W1[NH1 + i] + lm * W1[2 * NH1 + i]
               + dm * W1[3 * NH1 + i] + cc * W1[4 * NH1 + i];
    }
    float rb2[NH2], rw3[NH2];
#pragma unroll
    for (int k = 0; k < NH2; k++) { rb2[k] = b2[k]; rw3[k] = W3[k]; }
    const float rb3 = b3[0];

    // Forcing pipeline: cur, next, fetch (distance-2 DRAM prefetch).
    const float2* pe_ptr = p_and_e + bas;
    float2 pe_cur = pe_ptr[0];
    float2 pe_nxt = pe_ptr[NBASIN];

    // pre[] for t=0
    {
        const float p0 = fmaxf(pe_cur.x, 0.0f);
        const float e0 = fmaxf(pe_cur.y, 0.0f);
#pragma unroll
        for (int i = 0; i < NH1; i++)
            pre[i] = h1b[i] + p0 * sW6[i] + e0 * sW7[i];
    }

    float4* out_ptr = out + bas;

#pragma unroll 1
    for (int t = 0; t < T_STEPS; t++) {
        const float prcp = fmaxf(pe_cur.x, 0.0f);
        const float pet  = fmaxf(pe_cur.y, 0.0f);
        const float kpet = kc * pet;
        const float w0c  = fminf(fmaxf(w, 0.0f), wm_eps);

        // w0c-dependent MUFU chain starts immediately (off the MLP path).
        const float frac   = fminf(fmaxf(fmaf(-w0c, inv_wm, 1.0f), EPSV), 1.0f);
        const float a_xaj  = wmm * (1.0f - ex2f(inv_b1 * lg2f(frac)));
        const float r_base = w0c - wm;               // r_full = pe_net + r_base

        // ---- layer 1: 16 FFMA only (pre[] carries the forcing terms) ----
        float h[NH1];
#pragma unroll
        for (int i = 0; i < NH1; i++)
            h[i] = fmaxf(fmaf(w0c, w5[i], pre[i]), 0.0f);

        // ---- layer 2: 16x8 scalar matvec, 8 independent accumulators ----
        float a0 = rb2[0], a1 = rb2[1], a2 = rb2[2], a3 = rb2[3];
        float a4 = rb2[4], a5 = rb2[5], a6 = rb2[6], a7 = rb2[7];
#pragma unroll
        for (int j = 0; j < NH1; j++) {
            const float4 wA = *reinterpret_cast<const float4*>(&sW2[j * NH2]);
            const float4 wB = *reinterpret_cast<const float4*>(&sW2[j * NH2 + 4]);
            const float hj = h[j];
            a0 = fmaf(hj, wA.x, a0); a1 = fmaf(hj, wA.y, a1);
            a2 = fmaf(hj, wA.z, a2); a3 = fmaf(hj, wA.w, a3);
            a4 = fmaf(hj, wB.x, a4); a5 = fmaf(hj, wB.y, a5);
            a6 = fmaf(hj, wB.z, a6); a7 = fmaf(hj, wB.w, a7);
        }

        // ---- layer 3 (scalar tree) ----
        float y0 = rb3 + fmaxf(a0, 0.0f) * rw3[0];
        float y1 = fmaxf(a1, 0.0f) * rw3[1];
        float y2 = fmaxf(a2, 0.0f) * rw3[2];
        float y3 = fmaxf(a3, 0.0f) * rw3[3];
        y0 += fmaxf(a4, 0.0f) * rw3[4];
        y1 += fmaxf(a5, 0.0f) * rw3[5];
        y2 += fmaxf(a6, 0.0f) * rw3[6];
        y3 += fmaxf(a7, 0.0f) * rw3[7];
        const float y = (y0 + y1) + (y2 + y3);

        // sigmoid * kc * pet (MUFU EX2 + MUFU RCP)
        const float ex = ex2f(-1.442695040888963f * y);
        const float e  = __fdividef(kpet, 1.0f + ex);

        // ==== tail shadow: next step's forcing-only work (independent ops
        // that fill the MUFU/chain stalls of the sigmoid + resid-pow below) ====
        const float prcp_n = fmaxf(pe_nxt.x, 0.0f);
        const float pet_n  = fmaxf(pe_nxt.y, 0.0f);
#pragma unroll
        for (int q = 0; q < 4; q++) {
            const float4 a6v = *reinterpret_cast<const float4*>(&sW6[4 * q]);
            const float4 a7v = *reinterpret_cast<const float4*>(&sW7[4 * q]);
            pre[4 * q + 0] = h1b[4 * q + 0] + prcp_n * a6v.x + pet_n * a7v.x;
            pre[4 * q + 1] = h1b[4 * q + 1] + prcp_n * a6v.y + pet_n * a7v.y;
            pre[4 * q + 2] = h1b[4 * q + 2] + prcp_n * a6v.z + pet_n * a7v.z;
            pre[4 * q + 3] = h1b[4 * q + 3] + prcp_n * a6v.w + pet_n * a7v.w;
        }
        float2 pe_fetch = pe_nxt;
        if (t + 2 < T_STEPS) pe_fetch = pe_ptr[(size_t)(t + 2) * NBASIN];

        // ---- XAJ water balance ----
        const float pd     = prcp - e;
        const float pe_net = fmaxf(pd, 0.0f);
        const float resid  = fminf(fmaxf(fmaf(-(pe_net + a_xaj), inv_wmm, 1.0f), 0.0f), 1.0f);
        // resid==0 exactly when pe_net + a >= wmm; ex2(one_b*lg2(0)) = 0,
        // so this is branchlessly identical to the reference's where().
        const float rp  = ex2f(one_b * lg2f(resid));
        const float r   = fmaxf(pe_net + r_base + wm * rp, 0.0f);
        const float rim = pe_net * im;

        w = fminf(fmaxf(w0c + pd - r, 0.0f), wm_eps);

        out_ptr[0] = make_float4(r, rim, e, pe_net);
        out_ptr += NBASIN;

        // rotate the forcing pipeline
        pe_cur = pe_nxt;
        pe_nxt = pe_fetch;
    }
}

extern "C" void kernel_launch(void* const* d_in, const int* in_sizes, int n_in,
                              void* d_out, int out_size)
{
    (void)in_sizes; (void)n_in; (void)out_size;
    const float2* p_and_e = (const float2*)d_in[0];
    const float*  kc = (const float*)d_in[1];
    const float*  um = (const float*)d_in[2];
    const float*  lm = (const float*)d_in[3];
    const float*  dm = (const float*)d_in[4];
    const float*  b  = (const float*)d_in[5];
    const float*  im = (const float*)d_in[6];
    const float*  c  = (const float*)d_in[7];
    const float*  w0 = (const float*)d_in[8];
    const float*  W1 = (const float*)d_in[9];
    const float*  b1 = (const float*)d_in[10];
    const float*  W2 = (const float*)d_in[11];
    const float*  b2 = (const float*)d_in[12];
    const float*  W3 = (const float*)d_in[13];
    const float*  b3 = (const float*)d_in[14];
    float4* out = (float4*)d_out;

    // 16384 threads = 512 warps, 1 basin/thread, 4 warps/SM on 128 SMs
    // (R1-proven shape: lowest per-basin op count, max SMSP coverage).
    xaj_dpl8_kernel<<<128, 128>>>(p_and_e, kc, um, lm, dm, b, im, c, w0,
                                  W1, b1, W2, b2, W3, b3, out);
}